// round 2
// baseline (speedup 1.0000x reference)
#include <cuda_runtime.h>
#include <cuda_bf16.h>

// VariableGroupNorm: N=32, C=256, H=W=56, G=32, ragged groups (4/12 channels).
// One CTA per (n, g). Each group's data is a contiguous span of
// group_size*3136 floats (12.25 KB..147 KB): pass 1 = block-local sum/sumsq
// reduction (cached loads), pass 2 = fused scale+shift apply with streaming
// loads (last use) + streaming stores (write-only output must not evict x
// from L2). Minimum DRAM traffic: 1 read + 1 write = 205.5 MB.

#define NGROUPS 32
#define NCHAN   256
#define HW      3136
#define HW4     784      // HW / 4
#define EPSV    1e-5f
#define TPB     256

__global__ __launch_bounds__(TPB)
void vgn_fused_kernel(const float* __restrict__ x,
                      const float* __restrict__ gamma,
                      const float* __restrict__ beta,
                      const int*   __restrict__ gs_raw,
                      float* __restrict__ out)
{
    __shared__ int   s_off;
    __shared__ int   s_cnt;
    __shared__ float s_red[16];
    __shared__ float s_scale;
    __shared__ float s_shift;

    const int b = blockIdx.x;
    const int n = b >> 5;       // batch index
    const int g = b & 31;       // group index

    if (threadIdx.x == 0) {
        // Dtype hedge: group_sizes may land as int32 or int64 (low words).
        // If the sum of the first 32 int32 words == NCHAN it's int32;
        // otherwise assume little-endian int64 and stride by 2.
        int sum1 = 0;
        #pragma unroll
        for (int i = 0; i < NGROUPS; ++i) sum1 += gs_raw[i];
        const int stride = (sum1 == NCHAN) ? 1 : 2;
        int off = 0;
        for (int i = 0; i < g; ++i) off += gs_raw[i * stride];
        s_off = off;
        s_cnt = gs_raw[g * stride];
    }
    __syncthreads();

    const int c0 = s_off;
    const int cs = s_cnt;
    const size_t base = (size_t)(n * NCHAN + c0) * HW;
    const float4* __restrict__ xb = reinterpret_cast<const float4*>(x + base);
    float4* __restrict__       ob = reinterpret_cast<float4*>(out + base);
    const int nvec = cs * HW4;  // float4 count for this group

    // ---- Pass 1: sum / sumsq over the contiguous group span (cached) ----
    float s = 0.0f, sq = 0.0f;
    for (int i = threadIdx.x; i < nvec; i += TPB) {
        const float4 v = xb[i];
        s  += (v.x + v.y) + (v.z + v.w);
        sq += (v.x * v.x + v.y * v.y) + (v.z * v.z + v.w * v.w);
    }

    // warp reduce
    #pragma unroll
    for (int o = 16; o > 0; o >>= 1) {
        s  += __shfl_xor_sync(0xffffffffu, s,  o);
        sq += __shfl_xor_sync(0xffffffffu, sq, o);
    }
    const int wid = threadIdx.x >> 5;
    const int lid = threadIdx.x & 31;
    if (lid == 0) { s_red[wid] = s; s_red[8 + wid] = sq; }
    __syncthreads();

    if (threadIdx.x == 0) {
        float ts = 0.0f, tq = 0.0f;
        #pragma unroll
        for (int w = 0; w < TPB / 32; ++w) { ts += s_red[w]; tq += s_red[8 + w]; }
        const float cnt  = (float)cs * (float)HW;
        const float mean = ts / cnt;
        const float var  = tq / cnt - mean * mean;
        const float sc   = gamma[g] * rsqrtf(var + EPSV);
        s_scale = sc;
        s_shift = beta[g] - mean * sc;
    }
    __syncthreads();

    const float sc = s_scale;
    const float sh = s_shift;

    // ---- Pass 2: apply. Streaming loads (last use of x lines) and
    // streaming stores (write-only out must not evict x from L2). ----
    for (int i = threadIdx.x; i < nvec; i += TPB) {
        float4 v = __ldcs(&xb[i]);
        v.x = fmaf(v.x, sc, sh);
        v.y = fmaf(v.y, sc, sh);
        v.z = fmaf(v.z, sc, sh);
        v.w = fmaf(v.w, sc, sh);
        __stcs(&ob[i], v);
    }
}

extern "C" void kernel_launch(void* const* d_in, const int* in_sizes, int n_in,
                              void* d_out, int out_size)
{
    const float* x     = (const float*)d_in[0];
    const float* gamma = (const float*)d_in[1];
    const float* beta  = (const float*)d_in[2];
    const int*   gs    = (const int*)d_in[3];
    float*       out   = (float*)d_out;

    const int nbatch  = in_sizes[0] / (NCHAN * HW);  // 32
    const int nblocks = nbatch * NGROUPS;            // 1024

    vgn_fused_kernel<<<nblocks, TPB>>>(x, gamma, beta, gs, out);
}

// round 5
// speedup vs baseline: 1.2184x; 1.2184x over previous
#include <cuda_runtime.h>
#include <cuda_bf16.h>

// VariableGroupNorm: N=32, C=256, H=W=56, G=32, ragged groups (4/12 channels).
// One CTA per (n, g); group data is a contiguous span (12.25 KB..147 KB).
// Pass 1: sum/sumsq, x4 register-blocked (4 independent accumulator pairs ->
// 4 LDG.128 in flight per warp; R2 measured regs=32 / DRAM 49.7% / issue 16%
// = latency-bound). Pass 2: fused scale+shift, streaming loads (last use) +
// streaming stores (write-only out must not evict x from L2).
// CTA schedule: 12-channel groups first (bids [0, nb/2)), 4-channel groups
// last, so the wave-2 tail is filled by cheap CTAs (3:1 cost ratio).
// Min DRAM traffic: 205.5 MB -> ~32 us floor at ~6.4 TB/s.

#define NGROUPS 32
#define NCHAN   256
#define HW      3136
#define HW4     784      // HW / 4
#define EPSV    1e-5f
#define TPB     256

__global__ __launch_bounds__(TPB)
void vgn_fused_kernel(const float* __restrict__ x,
                      const float* __restrict__ gamma,
                      const float* __restrict__ beta,
                      const int*   __restrict__ gs_raw,
                      float* __restrict__ out)
{
    __shared__ int   s_off;
    __shared__ int   s_cnt;
    __shared__ float s_red[16];
    __shared__ float s_scale;
    __shared__ float s_shift;

    // Big-groups-first schedule: alternating sizes [4,12,4,12,...] means odd g
    // are the heavy (12-ch) groups. Map the first half of bids to odd g.
    const int b    = blockIdx.x;
    const int half = gridDim.x >> 1;                  // 512
    int n, g;
    if (b < half) { n = b / (NGROUPS / 2);           g = (((b % (NGROUPS / 2)) << 1) | 1); }
    else          { const int b2 = b - half;
                    n = b2 / (NGROUPS / 2);          g = ((b2 % (NGROUPS / 2)) << 1); }

    if (threadIdx.x == 0) {
        // Dtype hedge: group_sizes may land as int32 or int64 (low words).
        // If the sum of the first 32 int32 words == NCHAN it's int32;
        // otherwise assume little-endian int64 and stride by 2.
        int sum1 = 0;
        #pragma unroll
        for (int i = 0; i < NGROUPS; ++i) sum1 += gs_raw[i];
        const int stride = (sum1 == NCHAN) ? 1 : 2;
        int off = 0;
        for (int i = 0; i < g; ++i) off += gs_raw[i * stride];
        s_off = off;
        s_cnt = gs_raw[g * stride];
    }
    __syncthreads();

    const int c0 = s_off;
    const int cs = s_cnt;
    const size_t base = (size_t)(n * NCHAN + c0) * HW;
    const float4* __restrict__ xb = reinterpret_cast<const float4*>(x + base);
    float4* __restrict__       ob = reinterpret_cast<float4*>(out + base);
    const int nvec = cs * HW4;  // float4 count for this group

    // ---- Pass 1: sum / sumsq, x4 register-blocked for MLP ----
    float s0 = 0.f, s1 = 0.f, s2 = 0.f, s3 = 0.f;
    float q0 = 0.f, q1 = 0.f, q2 = 0.f, q3 = 0.f;

    int i = threadIdx.x;
    for (; i + 3 * TPB < nvec; i += 4 * TPB) {
        const float4 a = __ldg(&xb[i]);
        const float4 bb = __ldg(&xb[i + TPB]);
        const float4 c = __ldg(&xb[i + 2 * TPB]);
        const float4 d = __ldg(&xb[i + 3 * TPB]);
        s0 += (a.x + a.y) + (a.z + a.w);
        q0 += (a.x * a.x + a.y * a.y) + (a.z * a.z + a.w * a.w);
        s1 += (bb.x + bb.y) + (bb.z + bb.w);
        q1 += (bb.x * bb.x + bb.y * bb.y) + (bb.z * bb.z + bb.w * bb.w);
        s2 += (c.x + c.y) + (c.z + c.w);
        q2 += (c.x * c.x + c.y * c.y) + (c.z * c.z + c.w * c.w);
        s3 += (d.x + d.y) + (d.z + d.w);
        q3 += (d.x * d.x + d.y * d.y) + (d.z * d.z + d.w * d.w);
    }
    for (; i < nvec; i += TPB) {
        const float4 a = __ldg(&xb[i]);
        s0 += (a.x + a.y) + (a.z + a.w);
        q0 += (a.x * a.x + a.y * a.y) + (a.z * a.z + a.w * a.w);
    }
    float s  = (s0 + s1) + (s2 + s3);
    float sq = (q0 + q1) + (q2 + q3);

    // warp reduce
    #pragma unroll
    for (int o = 16; o > 0; o >>= 1) {
        s  += __shfl_xor_sync(0xffffffffu, s,  o);
        sq += __shfl_xor_sync(0xffffffffu, sq, o);
    }
    const int wid = threadIdx.x >> 5;
    const int lid = threadIdx.x & 31;
    if (lid == 0) { s_red[wid] = s; s_red[8 + wid] = sq; }
    __syncthreads();

    if (threadIdx.x == 0) {
        float ts = 0.0f, tq = 0.0f;
        #pragma unroll
        for (int w = 0; w < TPB / 32; ++w) { ts += s_red[w]; tq += s_red[8 + w]; }
        const float cnt  = (float)cs * (float)HW;
        const float mean = ts / cnt;
        const float var  = tq / cnt - mean * mean;
        const float sc   = gamma[g] * rsqrtf(var + EPSV);
        s_scale = sc;
        s_shift = beta[g] - mean * sc;
    }
    __syncthreads();

    const float sc = s_scale;
    const float sh = s_shift;

    // ---- Pass 2: apply, x4 unrolled; loads batched before compute, stores
    // after. Streaming loads (last use of x lines), streaming stores
    // (write-only out must not evict x from L2). ----
    i = threadIdx.x;
    for (; i + 3 * TPB < nvec; i += 4 * TPB) {
        float4 a = __ldcs(&xb[i]);
        float4 bb = __ldcs(&xb[i + TPB]);
        float4 c = __ldcs(&xb[i + 2 * TPB]);
        float4 d = __ldcs(&xb[i + 3 * TPB]);
        a.x = fmaf(a.x, sc, sh); a.y = fmaf(a.y, sc, sh);
        a.z = fmaf(a.z, sc, sh); a.w = fmaf(a.w, sc, sh);
        bb.x = fmaf(bb.x, sc, sh); bb.y = fmaf(bb.y, sc, sh);
        bb.z = fmaf(bb.z, sc, sh); bb.w = fmaf(bb.w, sc, sh);
        c.x = fmaf(c.x, sc, sh); c.y = fmaf(c.y, sc, sh);
        c.z = fmaf(c.z, sc, sh); c.w = fmaf(c.w, sc, sh);
        d.x = fmaf(d.x, sc, sh); d.y = fmaf(d.y, sc, sh);
        d.z = fmaf(d.z, sc, sh); d.w = fmaf(d.w, sc, sh);
        __stcs(&ob[i], a);
        __stcs(&ob[i + TPB], bb);
        __stcs(&ob[i + 2 * TPB], c);
        __stcs(&ob[i + 3 * TPB], d);
    }
    for (; i < nvec; i += TPB) {
        float4 a = __ldcs(&xb[i]);
        a.x = fmaf(a.x, sc, sh); a.y = fmaf(a.y, sc, sh);
        a.z = fmaf(a.z, sc, sh); a.w = fmaf(a.w, sc, sh);
        __stcs(&ob[i], a);
    }
}

extern "C" void kernel_launch(void* const* d_in, const int* in_sizes, int n_in,
                              void* d_out, int out_size)
{
    const float* x     = (const float*)d_in[0];
    const float* gamma = (const float*)d_in[1];
    const float* beta  = (const float*)d_in[2];
    const int*   gs    = (const int*)d_in[3];
    float*       out   = (float*)d_out;

    const int nbatch  = in_sizes[0] / (NCHAN * HW);  // 32
    const int nblocks = nbatch * NGROUPS;            // 1024

    vgn_fused_kernel<<<nblocks, TPB>>>(x, gamma, beta, gs, out);
}